// round 2
// baseline (speedup 1.0000x reference)
#include <cuda_runtime.h>
#include <math.h>

#define BATCH 64
#define SEQ   512
#define EMBED 256
#define HID   512
#define GD    768     // HID + EMBED
#define NCLS  4

#define NBLK  128     // 2 batch halves x 64 column groups
#define NTHR  256
#define BG    32      // batch rows per CTA
#define JG    8       // hidden units per CTA
#define ND    32      // dot-columns per CTA = 4 gates * JG
#define RS    772     // padded row stride in floats (conflict-free LDS.128 phases)
#define K4    192     // GD / 4 (float4 count per row)

#define SMEM_FLOATS (ND*RS + BG*RS + ND + BG*ND*2)
#define SMEM_BYTES  (SMEM_FLOATS * 4)

// persistent scratch (allocation-free rule: __device__ globals)
__device__ float g_h[2][BATCH*HID];
__device__ float g_maxh[BATCH*HID];
__device__ unsigned long long g_cnt;   // monotonically increasing barrier ticket counter

__device__ __forceinline__ float sigf(float x)     { return 1.0f / (1.0f + __expf(-x)); }
__device__ __forceinline__ float tanhfast(float x) { return 2.0f / (1.0f + __expf(-2.0f*x)) - 1.0f; }

// Ticket grid barrier: counter never resets, so it is safe across graph replays
// (every barrier round consumes exactly NBLK tickets; 64-bit never wraps).
__device__ __forceinline__ void grid_barrier() {
    __threadfence();
    __syncthreads();
    if (threadIdx.x == 0) {
        unsigned long long ticket = atomicAdd(&g_cnt, 1ULL);
        unsigned long long target = (ticket / NBLK + 1ULL) * (unsigned long long)NBLK;
        while (*((volatile unsigned long long*)&g_cnt) < target) { }
    }
    __syncthreads();
    __threadfence();
}

extern "C" __global__ void __launch_bounds__(NTHR, 1)
lstm_persistent(const int*   __restrict__ ids,
                const float* __restrict__ emb,
                const float* __restrict__ Wf, const float* __restrict__ bf,
                const float* __restrict__ Wi, const float* __restrict__ bi,
                const float* __restrict__ Wo, const float* __restrict__ bo,
                const float* __restrict__ Wc, const float* __restrict__ bc,
                const float* __restrict__ fcw, const float* __restrict__ fcb,
                float* __restrict__ out)
{
    extern __shared__ float sm[];
    float* w_s    = sm;                    // [ND][RS]  weight slice (resident all steps)
    float* inp_s  = w_s   + ND*RS;         // [BG][RS]  staged inp = [h | x_t]
    float* bias_s = inp_s + BG*RS;         // [ND]
    float* part_s = bias_s + ND;           // [BG][ND][2] split-K partials

    const int tid = threadIdx.x;
    const int cta = blockIdx.x;
    const int b0  = (cta & 1) * BG;        // batch half
    const int j0  = (cta >> 1) * JG;       // hidden-unit group

    const float* Wg[4]  = {Wf, Wi, Wo, Wc};
    const float* bgp[4] = {bf, bi, bo, bc};

    // ---- one-time: load weight slice into SMEM (d = gate*8 + jj) ----
    for (int idx = tid; idx < ND*K4; idx += NTHR) {
        int d  = idx / K4;
        int kk = idx - d*K4;
        int g  = d >> 3, jj = d & 7;
        float4 v = ((const float4*)(Wg[g] + (size_t)(j0 + jj) * GD))[kk];
        ((float4*)(w_s + d*RS))[kk] = v;
    }
    if (tid < ND) {
        int g = tid >> 3, jj = tid & 7;
        bias_s[tid] = bgp[g][j0 + jj];
    }
    // zero the h(0) region this CTA owns (fresh every launch / graph replay)
    for (int idx = tid; idx < BG*JG; idx += NTHR) {
        int r = idx >> 3, jj = idx & 7;
        g_h[0][(b0 + r)*HID + j0 + jj] = 0.0f;
    }

    // compute-phase mapping: 8 warps = 4 row-groups x 2 K-segments
    const int warp = tid >> 5;
    const int lane = tid & 31;             // lane == dot-column d
    const int kseg = warp >> 2;            // 0 or 1 (K split)
    const int r0   = (warp & 3) * 8;       // local batch row base (8 rows/warp)

    // epilogue mapping: one thread per (batch row, hidden unit)
    const int eb  = tid >> 3;              // 0..31
    const int ejj = tid & 7;               // 0..7

    float cst  = 0.0f;                     // cell state, register-resident
    float mmax = -INFINITY;                // running max of h over time

    grid_barrier();                        // h(0) visible everywhere

    for (int t = 0; t < SEQ; t++) {
        const float* hcur  = g_h[t & 1];
        float*       hnext = g_h[(t + 1) & 1];

        // ---- stage inp = [h_prev (512) | embedding[ids[b,t]] (256)] ----
        for (int idx = tid; idx < BG*K4; idx += NTHR) {
            int row = idx / K4;
            int kk  = idx - row*K4;
            float4 v;
            if (kk < 128) {
                v = ((const float4*)(hcur + (size_t)(b0 + row) * HID))[kk];
            } else {
                int id = ids[(b0 + row)*SEQ + t];
                v = ((const float4*)(emb + (size_t)id * EMBED))[kk - 128];
            }
            ((float4*)(inp_s + row*RS))[kk] = v;
        }
        __syncthreads();

        // ---- split-K GEMM: each lane owns column d, 8 batch rows, half of K ----
        {
            float acc[8] = {0.f,0.f,0.f,0.f,0.f,0.f,0.f,0.f};
            const float4* w4 = (const float4*)(w_s + lane*RS) + kseg*96;
            const float*  ib = inp_s + r0*RS + kseg*384;
            #pragma unroll 2
            for (int kk = 0; kk < 96; kk++) {
                float4 w = w4[kk];
                #pragma unroll
                for (int r = 0; r < 8; r++) {
                    float4 x = ((const float4*)(ib + r*RS))[kk];
                    acc[r] = fmaf(w.x, x.x, fmaf(w.y, x.y, fmaf(w.z, x.z, fmaf(w.w, x.w, acc[r]))));
                }
            }
            #pragma unroll
            for (int r = 0; r < 8; r++)
                part_s[(r0 + r)*(ND*2) + lane*2 + kseg] = acc[r];
        }
        __syncthreads();

        // ---- epilogue: combine partials, gates, state update ----
        {
            const float* pb = part_s + eb*(ND*2);
            float pf = pb[(0*8 + ejj)*2] + pb[(0*8 + ejj)*2 + 1] + bias_s[ 0 + ejj];
            float pi = pb[(1*8 + ejj)*2] + pb[(1*8 + ejj)*2 + 1] + bias_s[ 8 + ejj];
            float po = pb[(2*8 + ejj)*2] + pb[(2*8 + ejj)*2 + 1] + bias_s[16 + ejj];
            float pg = pb[(3*8 + ejj)*2] + pb[(3*8 + ejj)*2 + 1] + bias_s[24 + ejj];
            float f  = sigf(pf);
            float iv = sigf(pi);
            float o  = sigf(po);
            float gg = tanhfast(pg);
            cst = f*cst + iv*gg;
            float h = o * tanhfast(cst);
            mmax = fmaxf(mmax, h);
            hnext[(size_t)(b0 + eb)*HID + j0 + ejj] = h;
        }
        grid_barrier();
    }

    // ---- max-over-time result out, then tiny FC on CTA 0 ----
    g_maxh[(size_t)(b0 + eb)*HID + j0 + ejj] = mmax;
    grid_barrier();

    if (cta == 0) {
        int b  = tid >> 2;
        int ci = tid & 3;
        const float4* a4 = (const float4*)(g_maxh + (size_t)b * HID);
        const float4* w4 = (const float4*)(fcw + (size_t)ci * HID);
        float acc = fcb[ci];
        #pragma unroll 4
        for (int k = 0; k < HID/4; k++) {
            float4 a = a4[k], w = w4[k];
            acc += a.x*w.x + a.y*w.y + a.z*w.z + a.w*w.w;
        }
        out[b*NCLS + ci] = acc;
    }
}

extern "C" void kernel_launch(void* const* d_in, const int* in_sizes, int n_in,
                              void* d_out, int out_size)
{
    const int*   ids = (const int*)  d_in[0];
    const float* emb = (const float*)d_in[1];
    const float* Wf  = (const float*)d_in[2];
    const float* bf  = (const float*)d_in[3];
    const float* Wi  = (const float*)d_in[4];
    const float* bi  = (const float*)d_in[5];
    const float* Wo  = (const float*)d_in[6];
    const float* bo  = (const float*)d_in[7];
    const float* Wc  = (const float*)d_in[8];
    const float* bc  = (const float*)d_in[9];
    const float* fcw = (const float*)d_in[10];
    const float* fcb = (const float*)d_in[11];
    float* out = (float*)d_out;

    cudaFuncSetAttribute(lstm_persistent,
                         cudaFuncAttributeMaxDynamicSharedMemorySize, SMEM_BYTES);
    lstm_persistent<<<NBLK, NTHR, SMEM_BYTES>>>(ids, emb, Wf, bf, Wi, bi,
                                                Wo, bo, Wc, bc, fcw, fcb, out);
}

// round 4
// speedup vs baseline: 1.4361x; 1.4361x over previous
#include <cuda_runtime.h>
#include <math.h>

#define BATCH 64
#define SEQ   512
#define EMBED 256
#define HID   512
#define GD    768     // HID + EMBED
#define NCLS  4

#define NBLK  128     // 2 batch halves x 64 column groups
#define NTHR  256
#define BG    32      // batch rows per CTA
#define ND    32      // dot-columns per CTA = 4 gates * 8 hidden units
#define K4T   192     // GD / 4 (float4 count per row)

// SMEM: w[32][768] + inp[32][768] (XOR-swizzled, no padding) + 4 partial sets + bias
#define SM_W    0
#define SM_INP  (32*768)
#define SM_PART (SM_INP + 32*768)
#define SM_BIAS (SM_PART + 4*1024)
#define SMEM_FLOATS (SM_BIAS + 32)
#define SMEM_BYTES  (SMEM_FLOATS * 4)

__device__ float g_h[2][BATCH*HID];
__device__ float g_maxh[BATCH*HID];
__device__ unsigned long long g_cnt;   // monotonically increasing ticket counter

__device__ __forceinline__ float sigf(float x)     { return 1.0f / (1.0f + __expf(-x)); }
__device__ __forceinline__ float tanhfast(float x) { return 2.0f / (1.0f + __expf(-2.0f*x)) - 1.0f; }

// packed fp32x2 FMA (FFMA2): d.{lo,hi} += a.{lo,hi} * b.{lo,hi}
__device__ __forceinline__ void fma2(unsigned long long &d,
                                     unsigned long long a, unsigned long long b) {
    asm("fma.rn.f32x2 %0, %1, %2, %0;" : "+l"(d) : "l"(a), "l"(b));
}
__device__ __forceinline__ float sum2(unsigned long long v) {
    float lo, hi;
    asm("mov.b64 {%0,%1}, %2;" : "=f"(lo), "=f"(hi) : "l"(v));
    return lo + hi;
}

// Ticket grid barrier (safe across graph replays: counter never resets).
__device__ __forceinline__ void grid_barrier() {
    __threadfence();
    __syncthreads();
    if (threadIdx.x == 0) {
        unsigned long long ticket = atomicAdd(&g_cnt, 1ULL);
        unsigned long long target = (ticket / NBLK + 1ULL) * (unsigned long long)NBLK;
        while (*((volatile unsigned long long*)&g_cnt) < target) { }
    }
    __syncthreads();
    __threadfence();
}

extern "C" __global__ void __launch_bounds__(NTHR, 1)
lstm_persistent(const int*   __restrict__ ids,
                const float* __restrict__ emb,
                const float* __restrict__ Wf, const float* __restrict__ bf,
                const float* __restrict__ Wi, const float* __restrict__ bi,
                const float* __restrict__ Wo, const float* __restrict__ bo,
                const float* __restrict__ Wc, const float* __restrict__ bc,
                const float* __restrict__ fcw, const float* __restrict__ fcb,
                float* __restrict__ out)
{
    extern __shared__ float sm[];
    float* w_s    = sm + SM_W;
    float* inp_s  = sm + SM_INP;
    float* part_s = sm + SM_PART;   // 4 sets x [32 cols][32 rows] col-major
    float* bias_s = sm + SM_BIAS;

    const int tid  = threadIdx.x;
    const int cta  = blockIdx.x;
    const int b0   = (cta & 1) * BG;        // batch half
    const int j0   = (cta >> 1) * 8;        // hidden-unit group (8 units)
    const int wid  = tid >> 5;
    const int lane = tid & 31;

    const float* Wg[4]  = {Wf, Wi, Wo, Wc};
    const float* bgp[4] = {bf, bi, bo, bc};

    // ---- one-time: weight slice into swizzled SMEM (col d = gate*8 + jj) ----
    for (int idx = tid; idx < ND*K4T; idx += NTHR) {
        int d  = idx / K4T;
        int k4 = idx - d*K4T;
        int g  = d >> 3, jj = d & 7;
        float4 v = ((const float4*)(Wg[g] + (size_t)(j0 + jj) * GD))[k4];
        *(float4*)(w_s + d*GD + ((k4 ^ ((d >> 2) & 7)) << 2)) = v;
    }
    if (tid < ND) {
        int g = tid >> 3, jj = tid & 7;
        bias_s[tid] = bgp[g][j0 + jj];
    }
    // zero the h(0) region this CTA owns
    for (int idx = tid; idx < BG*8; idx += NTHR) {
        int r = idx >> 3, jj = idx & 7;
        g_h[0][(b0 + r)*HID + j0 + jj] = 0.0f;
    }

    // compute-phase lane mapping: rg = row group (4 rows), cg = col group (8 cols)
    const int rg = lane >> 2;               // 0..7  -> rows 4*rg .. 4*rg+3
    const int cg = lane & 3;                // 0..3  -> cols 8*cg .. 8*cg+7
    const int kb = wid * 24;                // k4 segment base (8-way split-K)
    const int s0 = (2*cg) & 7;              // w swizzle for cols 8cg..8cg+3
    const int s1 = (2*cg + 1) & 7;          // w swizzle for cols 8cg+4..8cg+7
    const float* xr0 = inp_s + (4*rg) * GD;
    const float* wc0 = w_s   + (8*cg) * GD;

    // staging lane mapping: warp owns 4 rows (stride 4), lane covers k-octet
    const int dr    = lane >> 3;            // 0..3
    const int dk    = lane & 7;             // 0..7
    const int rbase = (wid & 3) + (wid >> 2) * 16;
    const int srow_ = rbase + 4*dr;         // this lane's staging row (0..31)
    const int ssw   = srow_ >> 2;           // its swizzle key
    float* sdst = inp_s + srow_ * GD;

    // epilogue mapping: one thread per (batch row, hidden unit)
    const int eb  = tid >> 3;               // 0..31
    const int ejj = tid & 7;                // 0..7

    float cst  = 0.0f;
    float mmax = -INFINITY;

    grid_barrier();                          // h(0) visible everywhere

    for (int t = 0; t < SEQ; t++) {
        const float* hcur  = g_h[t & 1];
        float*       hnext = g_h[(t + 1) & 1];

        // ---- stage inp = [h_prev (512) | embedding (256)] into swizzled SMEM ----
        {
            const float4* hrow = (const float4*)(hcur + (size_t)(b0 + srow_) * HID);
            #pragma unroll
            for (int oct = 0; oct < 16; oct++) {
                int k4 = oct*8 + dk;
                *(float4*)(sdst + ((k4 ^ ssw) << 2)) = hrow[k4];
            }
            int id = ids[(b0 + srow_)*SEQ + t];
            const float4* erow = (const float4*)(emb + (size_t)id * EMBED);
            #pragma unroll
            for (int oct = 16; oct < 24; oct++) {
                int k4 = oct*8 + dk;
                *(float4*)(sdst + ((k4 ^ ssw) << 2)) = erow[k4 - 128];
            }
        }
        __syncthreads();

        // ---- register-tiled GEMM: lane tile 4 rows x 8 cols, k-packed f32x2 acc ----
        unsigned long long acc[4][8];
        #pragma unroll
        for (int r = 0; r < 4; r++)
            #pragma unroll
            for (int c = 0; c < 8; c++) acc[r][c] = 0ULL;

        #pragma unroll 2
        for (int kk = 0; kk < 24; kk++) {
            int k4 = kb + kk;
            int ox = (k4 ^ rg) << 2;
            int o0 = (k4 ^ s0) << 2;
            int o1 = (k4 ^ s1) << 2;
            ulonglong2 xv[4];
            #pragma unroll
            for (int r = 0; r < 4; r++)
                xv[r] = *(const ulonglong2*)(xr0 + r*GD + ox);
            #pragma unroll
            for (int c = 0; c < 8; c++) {
                ulonglong2 wv = *(const ulonglong2*)(wc0 + c*GD + (c < 4 ? o0 : o1));
                #pragma unroll
                for (int r = 0; r < 4; r++) {
                    fma2(acc[r][c], xv[r].x, wv.x);
                    fma2(acc[r][c], xv[r].y, wv.y);
                }
            }
        }

        float accf[4][8];
        #pragma unroll
        for (int r = 0; r < 4; r++)
            #pragma unroll
            for (int c = 0; c < 8; c++) accf[r][c] = sum2(acc[r][c]);

        // ---- split-K tree reduction through SMEM (sets are [col][row] col-major) ----
        if (wid >= 4) {
            float* sp = part_s + (wid - 4)*1024;
            #pragma unroll
            for (int c = 0; c < 8; c++)
                *(float4*)(sp + (8*cg + c)*32 + 4*rg) =
                    make_float4(accf[0][c], accf[1][c], accf[2][c], accf[3][c]);
        }
        __syncthreads();
        if (wid < 4) {
            const float* sp = part_s + wid*1024;
            #pragma unroll
            for (int c = 0; c < 8; c++) {
                float4 v = *(const float4*)(sp + (8*cg + c)*32 + 4*rg);
                accf[0][c] += v.x; accf[1][c] += v.y; accf[2][c] += v.z; accf[3][c] += v.w;
            }
        }
        __syncthreads();
        if (wid == 2 || wid == 3) {
            float* sp = part_s + (wid - 2)*1024;
            #pragma unroll
            for (int c = 0; c < 8; c++)
                *(float4*)(sp + (8*cg + c)*32 + 4*rg) =
                    make_float4(accf[0][c], accf[1][c], accf[2][c], accf[3][c]);
        }
        __syncthreads();
        if (wid < 2) {
            const float* sp = part_s + wid*1024;
            #pragma unroll
            for (int c = 0; c < 8; c++) {
                float4 v = *(const float4*)(sp + (8*cg + c)*32 + 4*rg);
                accf[0][c] += v.x; accf[1][c] += v.y; accf[2][c] += v.z; accf[3][c] += v.w;
            }
        }
        __syncthreads();
        if (wid == 1) {
            float* sp = part_s;
            #pragma unroll
            for (int c = 0; c < 8; c++)
                *(float4*)(sp + (8*cg + c)*32 + 4*rg) =
                    make_float4(accf[0][c], accf[1][c], accf[2][c], accf[3][c]);
        }
        __syncthreads();
        if (wid == 0) {
            const float* sp = part_s;
            float fsum[4][8];
            #pragma unroll
            for (int c = 0; c < 8; c++) {
                float4 v = *(const float4*)(sp + (8*cg + c)*32 + 4*rg);
                fsum[0][c] = accf[0][c] + v.x;
                fsum[1][c] = accf[1][c] + v.y;
                fsum[2][c] = accf[2][c] + v.z;
                fsum[3][c] = accf[3][c] + v.w;
            }
            __syncwarp();
            // final sums -> row-major fin[r*32 + d] in set 1 (avoids RAW on set 0)
            float* fin = part_s + 1024;
            #pragma unroll
            for (int r = 0; r < 4; r++) {
                *(float4*)(fin + (4*rg + r)*32 + 8*cg)     =
                    make_float4(fsum[r][0], fsum[r][1], fsum[r][2], fsum[r][3]);
                *(float4*)(fin + (4*rg + r)*32 + 8*cg + 4) =
                    make_float4(fsum[r][4], fsum[r][5], fsum[r][6], fsum[r][7]);
            }
        }
        __syncthreads();

        // ---- epilogue: gates, state update, running max ----
        {
            const float* fin = part_s + 1024;
            float pf = fin[eb*32 +  0 + ejj] + bias_s[ 0 + ejj];
            float pi = fin[eb*32 +  8 + ejj] + bias_s[ 8 + ejj];
            float po = fin[eb*32 + 16 + ejj] + bias_s[16 + ejj];
            float pg = fin[eb*32 + 24 + ejj] + bias_s[24 + ejj];
            float f  = sigf(pf);
            float iv = sigf(pi);
            float o  = sigf(po);
            float gg = tanhfast(pg);
            cst = f*cst + iv*gg;
            float h = o * tanhfast(cst);
            mmax = fmaxf(mmax, h);
            hnext[(size_t)(b0 + eb)*HID + j0 + ejj] = h;
        }
        grid_barrier();
    }

    // ---- max-over-time out, then tiny FC on CTA 0 ----
    g_maxh[(size_t)(b0 + eb)*HID + j0 + ejj] = mmax;
    grid_barrier();

    if (cta == 0) {
        int b  = tid >> 2;
        int ci = tid & 3;
        const float4* a4 = (const float4*)(g_maxh + (size_t)b * HID);
        const float4* w4 = (const float4*)(fcw + (size_t)ci * HID);
        float acc = fcb[ci];
        #pragma unroll 4
        for (int k = 0; k < HID/4; k++) {
            float4 a = a4[k], w = w4[k];
            acc += a.x*w.x + a.y*w.y + a.z*w.z + a.w*w.w;
        }
        out[b*NCLS + ci] = acc;
    }
}

extern "C" void kernel_launch(void* const* d_in, const int* in_sizes, int n_in,
                              void* d_out, int out_size)
{
    const int*   ids = (const int*)  d_in[0];
    const float* emb = (const float*)d_in[1];
    const float* Wf  = (const float*)d_in[2];
    const float* bf  = (const float*)d_in[3];
    const float* Wi  = (const float*)d_in[4];
    const float* bi  = (const float*)d_in[5];
    const float* Wo  = (const float*)d_in[6];
    const float* bo  = (const float*)d_in[7];
    const float* Wc  = (const float*)d_in[8];
    const float* bc  = (const float*)d_in[9];
    const float* fcw = (const float*)d_in[10];
    const float* fcb = (const float*)d_in[11];
    float* out = (float*)d_out;

    cudaFuncSetAttribute(lstm_persistent,
                         cudaFuncAttributeMaxDynamicSharedMemorySize, SMEM_BYTES);
    lstm_persistent<<<NBLK, NTHR, SMEM_BYTES>>>(ids, emb, Wf, bf, Wi, bi,
                                                Wo, bo, Wc, bc, fcw, fcb, out);
}

// round 5
// speedup vs baseline: 1.8843x; 1.3121x over previous
#include <cuda_runtime.h>
#include <math.h>

#define BATCH 64
#define SEQ   512
#define EMBED 256
#define HID   512
#define GD    768     // HID + EMBED
#define NCLS  4

#define NBLK  128     // 2 batch halves x 64 column groups
#define NTHR  256
#define BG    32      // batch rows per CTA
#define ND    32      // dot-columns per CTA = 4 gates * 8 hidden units
#define K4T   192     // GD / 4 (float4 count per row)

// SMEM: w[32][768] + inp[32][768] (XOR-swizzled) + 8 partial sets + bias
#define SM_W       0
#define SM_INP     (32*768)
#define SM_PART    (SM_INP + 32*768)
#define SET_STRIDE 1056                 // 32 cols' x 33 (row-padded), %32==0
#define SM_BIAS    (SM_PART + 8*SET_STRIDE)
#define SMEM_FLOATS (SM_BIAS + 32)
#define SMEM_BYTES  (SMEM_FLOATS * 4)   // 230,528 B  (< 232,448 max)

__device__ float g_h[2][BATCH*HID];
__device__ float g_maxh[BATCH*HID];
__device__ unsigned long long g_cnt;    // monotonically increasing ticket counter

__device__ __forceinline__ float sigf(float x)     { return 1.0f / (1.0f + __expf(-x)); }
__device__ __forceinline__ float tanhfast(float x) { return 2.0f / (1.0f + __expf(-2.0f*x)) - 1.0f; }

// packed fp32x2 FMA (FFMA2)
__device__ __forceinline__ void fma2(unsigned long long &d,
                                     unsigned long long a, unsigned long long b) {
    asm("fma.rn.f32x2 %0, %1, %2, %0;" : "+l"(d) : "l"(a), "l"(b));
}
__device__ __forceinline__ float sum2(unsigned long long v) {
    float lo, hi;
    asm("mov.b64 {%0,%1}, %2;" : "=f"(lo), "=f"(hi) : "l"(v));
    return lo + hi;
}

// Fence-free grid barrier: release-atomic ticket + acquire poll.
// No __threadfence => no CCTL.IVALL L1 flush. Cross-CTA data (h) is
// always accessed via __ldcg (L2-direct), so L1 staleness is harmless.
__device__ __forceinline__ void grid_barrier() {
    __syncthreads();
    if (threadIdx.x == 0) {
        unsigned long long ticket;
        asm volatile("atom.release.gpu.add.u64 %0, [%1], %2;"
                     : "=l"(ticket) : "l"(&g_cnt), "l"(1ULL) : "memory");
        unsigned long long target = (ticket / NBLK + 1ULL) * (unsigned long long)NBLK;
        unsigned long long cur;
        do {
            asm volatile("ld.acquire.gpu.u64 %0, [%1];"
                         : "=l"(cur) : "l"(&g_cnt) : "memory");
        } while (cur < target);
    }
    __syncthreads();
}

__device__ __forceinline__ void loadx(ulonglong2 xv[4], const float* xr0, int k4, int rg) {
    int ox = ((k4 ^ rg) << 2);
    #pragma unroll
    for (int r = 0; r < 4; r++)
        xv[r] = *(const ulonglong2*)(xr0 + r*GD + ox);
}

__device__ __forceinline__ void gemm_step(unsigned long long acc[4][8],
                                          const ulonglong2 xv[4],
                                          const float* wc0, int o0, int o1) {
    #pragma unroll
    for (int c = 0; c < 8; c++) {
        ulonglong2 wv = *(const ulonglong2*)(wc0 + c*GD + (c < 4 ? o0 : o1));
        #pragma unroll
        for (int r = 0; r < 4; r++) {
            fma2(acc[r][c], xv[r].x, wv.x);
            fma2(acc[r][c], xv[r].y, wv.y);
        }
    }
}

extern "C" __global__ void __launch_bounds__(NTHR, 1)
lstm_persistent(const int*   __restrict__ ids,
                const float* __restrict__ emb,
                const float* __restrict__ Wf, const float* __restrict__ bf,
                const float* __restrict__ Wi, const float* __restrict__ bi,
                const float* __restrict__ Wo, const float* __restrict__ bo,
                const float* __restrict__ Wc, const float* __restrict__ bc,
                const float* __restrict__ fcw, const float* __restrict__ fcb,
                float* __restrict__ out)
{
    extern __shared__ float sm[];
    float* w_s    = sm + SM_W;
    float* inp_s  = sm + SM_INP;
    float* part_s = sm + SM_PART;
    float* bias_s = sm + SM_BIAS;

    const int tid  = threadIdx.x;
    const int cta  = blockIdx.x;
    const int b0   = (cta & 1) * BG;        // batch half
    const int j0   = (cta >> 1) * 8;        // hidden-unit group (8 units)
    const int wid  = tid >> 5;
    const int lane = tid & 31;

    const float* Wg[4]  = {Wf, Wi, Wo, Wc};
    const float* bgp[4] = {bf, bi, bo, bc};

    // ---- one-time: weight slice into swizzled SMEM (col d = gate*8 + jj) ----
    for (int idx = tid; idx < ND*K4T; idx += NTHR) {
        int d  = idx / K4T;
        int k4 = idx - d*K4T;
        int g  = d >> 3, jj = d & 7;
        float4 v = ((const float4*)(Wg[g] + (size_t)(j0 + jj) * GD))[k4];
        *(float4*)(w_s + d*GD + ((k4 ^ ((d >> 2) & 7)) << 2)) = v;
    }
    if (tid < ND) {
        int g = tid >> 3, jj = tid & 7;
        bias_s[tid] = bgp[g][j0 + jj];
    }
    // zero the h(0) region this CTA owns
    for (int idx = tid; idx < BG*8; idx += NTHR) {
        int r = idx >> 3, jj = idx & 7;
        g_h[0][(b0 + r)*HID + j0 + jj] = 0.0f;
    }

    // compute-phase lane mapping
    const int rg = lane >> 2;               // rows 4*rg..4*rg+3
    const int cg = lane & 3;                // cols 8*cg..8*cg+7
    const int kb = wid * 24;                // 8-way split-K segment base
    const int s0 = (2*cg) & 7;
    const int s1 = (2*cg + 1) & 7;
    const float* xr0 = inp_s + (4*rg) * GD;
    const float* wc0 = w_s   + (8*cg) * GD;

    // staging lane mapping
    const int dr    = lane >> 3;
    const int dk    = lane & 7;
    const int rbase = (wid & 3) + (wid >> 2) * 16;
    const int srow_ = rbase + 4*dr;
    const int ssw   = srow_ >> 2;
    float* sdst = inp_s + srow_ * GD;

    // epilogue mapping
    const int eb  = tid >> 3;               // 0..31
    const int ejj = tid & 7;                // 0..7

    float cst  = 0.0f;
    float mmax = -INFINITY;

    // ---- pre-stage embedding for t=0 ----
    {
        int id0 = ids[(b0 + srow_)*SEQ + 0];
        const float4* erow = (const float4*)(emb + (size_t)id0 * EMBED);
        #pragma unroll
        for (int o = 0; o < 8; o++) {
            int k4 = (16 + o)*8 + dk;
            *(float4*)(sdst + ((k4 ^ ssw) << 2)) = erow[o*8 + dk];
        }
    }

    grid_barrier();                          // h(0) + emb(0) visible

    for (int t = 0; t < SEQ; t++) {
        const float* hcur = g_h[t & 1];

        // ---- stage h_prev (512 floats) into swizzled SMEM (L2-direct) ----
        {
            const float4* hrow = (const float4*)(hcur + (size_t)(b0 + srow_) * HID);
            #pragma unroll
            for (int oct = 0; oct < 16; oct++) {
                int k4 = oct*8 + dk;
                *(float4*)(sdst + ((k4 ^ ssw) << 2)) = __ldcg(hrow + k4);
            }
        }
        __syncthreads();

        // ---- register-tiled split-K GEMM with x prefetch ----
        unsigned long long acc[4][8];
        #pragma unroll
        for (int r = 0; r < 4; r++)
            #pragma unroll
            for (int c = 0; c < 8; c++) acc[r][c] = 0ULL;

        {
            ulonglong2 xa[4], xb[4];
            loadx(xa, xr0, kb, rg);
            #pragma unroll
            for (int kk = 0; kk < 24; kk += 2) {
                loadx(xb, xr0, kb + kk + 1, rg);
                gemm_step(acc, xa, wc0, ((kb+kk)   ^ s0) << 2, ((kb+kk)   ^ s1) << 2);
                if (kk + 2 < 24) loadx(xa, xr0, kb + kk + 2, rg);
                gemm_step(acc, xb, wc0, ((kb+kk+1) ^ s0) << 2, ((kb+kk+1) ^ s1) << 2);
            }
        }

        // ---- one-shot partial store (conflict-free: bank = col'+row) ----
        {
            float* myset = part_s + wid*SET_STRIDE;
            #pragma unroll
            for (int c = 0; c < 8; c++)
                #pragma unroll
                for (int r = 0; r < 4; r++)
                    myset[(4*c + cg)*33 + 4*rg + r] = sum2(acc[r][c]);
        }
        __syncthreads();

        // ---- embedding prefetch for t+1 (long-latency loads issued first) ----
        float4 ev[8];
        const bool doemb = (t + 1 < SEQ);
        if (doemb) {
            int id1 = ids[(b0 + srow_)*SEQ + (t + 1)];
            const float4* erow = (const float4*)(emb + (size_t)id1 * EMBED);
            #pragma unroll
            for (int o = 0; o < 8; o++) ev[o] = erow[o*8 + dk];
        }

        // ---- epilogue: sum 8 segments, gates, state update ----
        {
            float pf = bias_s[ 0 + ejj];
            float pi = bias_s[ 8 + ejj];
            float po = bias_s[16 + ejj];
            float pg = bias_s[24 + ejj];
            #pragma unroll
            for (int s = 0; s < 8; s++) {
                const float* sp = part_s + s*SET_STRIDE + eb;
                pf += sp[(4*ejj + 0)*33];
                pi += sp[(4*ejj + 1)*33];
                po += sp[(4*ejj + 2)*33];
                pg += sp[(4*ejj + 3)*33];
            }
            float f  = sigf(pf);
            float iv = sigf(pi);
            float o  = sigf(po);
            float gg = tanhfast(pg);
            cst = f*cst + iv*gg;
            float h = o * tanhfast(cst);
            mmax = fmaxf(mmax, h);
            g_h[(t + 1) & 1][(size_t)(b0 + eb)*HID + j0 + ejj] = h;
        }

        // ---- store prefetched embedding into SMEM for t+1 ----
        if (doemb) {
            #pragma unroll
            for (int o = 0; o < 8; o++) {
                int k4 = (16 + o)*8 + dk;
                *(float4*)(sdst + ((k4 ^ ssw) << 2)) = ev[o];
            }
        }

        grid_barrier();
    }

    // ---- max-over-time out, then tiny FC on CTA 0 ----
    g_maxh[(size_t)(b0 + eb)*HID + j0 + ejj] = mmax;
    grid_barrier();

    if (cta == 0) {
        int b  = tid >> 2;
        int ci = tid & 3;
        const float4* a4 = (const float4*)(g_maxh + (size_t)b * HID);
        const float4* w4 = (const float4*)(fcw + (size_t)ci * HID);
        float acc = fcb[ci];
        #pragma unroll 4
        for (int k = 0; k < HID/4; k++) {
            float4 a = __ldcg(a4 + k);
            float4 w = w4[k];
            acc += a.x*w.x + a.y*w.y + a.z*w.z + a.w*w.w;
        }
        out[b*NCLS + ci] = acc;
    }
}

extern "C" void kernel_launch(void* const* d_in, const int* in_sizes, int n_in,
                              void* d_out, int out_size)
{
    const int*   ids = (const int*)  d_in[0];
    const float* emb = (const float*)d_in[1];
    const float* Wf  = (const float*)d_in[2];
    const float* bf  = (const float*)d_in[3];
    const float* Wi  = (const float*)d_in[4];
    const float* bi  = (const float*)d_in[5];
    const float* Wo  = (const float*)d_in[6];
    const float* bo  = (const float*)d_in[7];
    const float* Wc  = (const float*)d_in[8];
    const float* bc  = (const float*)d_in[9];
    const float* fcw = (const float*)d_in[10];
    const float* fcb = (const float*)d_in[11];
    float* out = (float*)d_out;

    cudaFuncSetAttribute(lstm_persistent,
                         cudaFuncAttributeMaxDynamicSharedMemorySize, SMEM_BYTES);
    lstm_persistent<<<NBLK, NTHR, SMEM_BYTES>>>(ids, emb, Wf, bf, Wi, bi,
                                                Wo, bo, Wc, bc, fcw, fcb, out);
}

// round 6
// speedup vs baseline: 2.0724x; 1.0999x over previous
#include <cuda_runtime.h>
#include <math.h>

#define BATCH 64
#define SEQ   512
#define EMBED 256
#define HID   512
#define GD    768     // HID + EMBED
#define NCLS  4

#define NBLK  128     // 2 batch halves x 64 column groups
#define NTHR  256
#define BG    32      // batch rows per CTA
#define ND    32      // dot-columns per CTA = 4 gates * 8 hidden units
#define K4T   192     // GD / 4 (float4 count per row)
#define HALF_CTAS 64

// SMEM: w[32][768] + inp[32][768] (XOR-swizzled) + 8 partial sets + bias
#define SM_W       0
#define SM_INP     (32*768)
#define SM_PART    (SM_INP + 32*768)
#define SET_STRIDE 1056                 // 32 cols' x 33 (row-padded)
#define SM_BIAS    (SM_PART + 8*SET_STRIDE)
#define SMEM_FLOATS (SM_BIAS + 32)
#define SMEM_BYTES  (SMEM_FLOATS * 4)   // 230,528 B

__device__ float g_h[2][BATCH*HID];
__device__ float g_maxh[BATCH*HID];
__device__ unsigned long long g_cnt;          // full-grid ticket counter (init/final)
__device__ unsigned long long g_half[64];     // per-half arrival counters, 256B apart (slots 0 and 32)

__device__ __forceinline__ float sigf(float x)     { return 1.0f / (1.0f + __expf(-x)); }
__device__ __forceinline__ float tanhfast(float x) { return 2.0f / (1.0f + __expf(-2.0f*x)) - 1.0f; }

__device__ __forceinline__ void fma2(unsigned long long &d,
                                     unsigned long long a, unsigned long long b) {
    asm("fma.rn.f32x2 %0, %1, %2, %0;" : "+l"(d) : "l"(a), "l"(b));
}
__device__ __forceinline__ float sum2(unsigned long long v) {
    float lo, hi;
    asm("mov.b64 {%0,%1}, %2;" : "=f"(lo), "=f"(hi) : "l"(v));
    return lo + hi;
}

// cp.async 16B, L2-only (.cg): required for h (cross-SM coherence), fine for emb
__device__ __forceinline__ void cp16_cg(unsigned int saddr, const void* g) {
    asm volatile("cp.async.cg.shared.global [%0], [%1], 16;" :: "r"(saddr), "l"(g));
}
#define CP_COMMIT()  asm volatile("cp.async.commit_group;" ::: "memory")
#define CP_WAITALL() asm volatile("cp.async.wait_all;"     ::: "memory")

// Full-grid ticket barrier (fence-free; used at init and finish only).
__device__ __forceinline__ void ticket_barrier() {
    __syncthreads();
    if (threadIdx.x == 0) {
        unsigned long long ticket;
        asm volatile("atom.release.gpu.add.u64 %0, [%1], %2;"
                     : "=l"(ticket) : "l"(&g_cnt), "l"(1ULL) : "memory");
        unsigned long long target = (ticket / NBLK + 1ULL) * (unsigned long long)NBLK;
        unsigned long long cur;
        do {
            asm volatile("ld.acquire.gpu.u64 %0, [%1];"
                         : "=l"(cur) : "l"(&g_cnt) : "memory");
        } while (cur < target);
    }
    __syncthreads();
}

// Per-half barrier: no-return release reduction + acquire poll against a
// per-replay base snapshot (monotonic counters => graph-replay safe).
__device__ __forceinline__ void half_barrier(unsigned long long* ctr,
                                             unsigned long long target) {
    __syncthreads();
    if (threadIdx.x == 0) {
        asm volatile("red.release.gpu.add.u64 [%0], %1;"
                     :: "l"(ctr), "l"(1ULL) : "memory");
        unsigned long long cur;
        do {
            asm volatile("ld.acquire.gpu.u64 %0, [%1];"
                         : "=l"(cur) : "l"(ctr) : "memory");
        } while (cur < target);
    }
    __syncthreads();
}

__device__ __forceinline__ void loadx(ulonglong2 xv[4], const float* xr0, int k4, int rg) {
    int ox = ((k4 ^ rg) << 2);
    #pragma unroll
    for (int r = 0; r < 4; r++)
        xv[r] = *(const ulonglong2*)(xr0 + r*GD + ox);
}

__device__ __forceinline__ void gemm_step(unsigned long long acc[4][8],
                                          const ulonglong2 xv[4],
                                          const float* wc0, int o0, int o1) {
    #pragma unroll
    for (int c = 0; c < 8; c++) {
        ulonglong2 wv = *(const ulonglong2*)(wc0 + c*GD + (c < 4 ? o0 : o1));
        #pragma unroll
        for (int r = 0; r < 4; r++) {
            fma2(acc[r][c], xv[r].x, wv.x);
            fma2(acc[r][c], xv[r].y, wv.y);
        }
    }
}

extern "C" __global__ void __launch_bounds__(NTHR, 1)
lstm_persistent(const int*   __restrict__ ids,
                const float* __restrict__ emb,
                const float* __restrict__ Wf, const float* __restrict__ bf,
                const float* __restrict__ Wi, const float* __restrict__ bi,
                const float* __restrict__ Wo, const float* __restrict__ bo,
                const float* __restrict__ Wc, const float* __restrict__ bc,
                const float* __restrict__ fcw, const float* __restrict__ fcb,
                float* __restrict__ out)
{
    extern __shared__ float sm[];
    float* w_s    = sm + SM_W;
    float* inp_s  = sm + SM_INP;
    float* part_s = sm + SM_PART;
    float* bias_s = sm + SM_BIAS;

    const int tid  = threadIdx.x;
    const int cta  = blockIdx.x;
    const int half = cta & 1;
    const int b0   = half * BG;             // batch half
    const int j0   = (cta >> 1) * 8;        // hidden-unit group (8 units)
    const int wid  = tid >> 5;
    const int lane = tid & 31;

    unsigned long long* hctr = &g_half[half * 32];   // 256B apart

    const float* Wg[4]  = {Wf, Wi, Wo, Wc};
    const float* bgp[4] = {bf, bi, bo, bc};

    // ---- one-time: weight slice into swizzled SMEM (col d = gate*8 + jj) ----
    for (int idx = tid; idx < ND*K4T; idx += NTHR) {
        int d  = idx / K4T;
        int k4 = idx - d*K4T;
        int g  = d >> 3, jj = d & 7;
        float4 v = ((const float4*)(Wg[g] + (size_t)(j0 + jj) * GD))[k4];
        *(float4*)(w_s + d*GD + ((k4 ^ ((d >> 2) & 7)) << 2)) = v;
    }
    if (tid < ND) {
        int g = tid >> 3, jj = tid & 7;
        bias_s[tid] = bgp[g][j0 + jj];
    }
    // zero the h(0) region this CTA owns
    for (int idx = tid; idx < BG*8; idx += NTHR) {
        int r = idx >> 3, jj = idx & 7;
        g_h[0][(b0 + r)*HID + j0 + jj] = 0.0f;
    }

    // compute-phase lane mapping
    const int rg = lane >> 2;               // rows 4*rg..4*rg+3
    const int cg = lane & 3;                // cols 8*cg..8*cg+7
    const int kb = wid * 24;                // 8-way split-K segment base
    const int s0 = (2*cg) & 7;
    const int s1 = (2*cg + 1) & 7;
    const float* xr0 = inp_s + (4*rg) * GD;
    const float* wc0 = w_s   + (8*cg) * GD;

    // staging lane mapping
    const int dr    = lane >> 3;
    const int dk    = lane & 7;
    const int rbase = (wid & 3) + (wid >> 2) * 16;
    const int srow_ = rbase + 4*dr;
    const int ssw   = srow_ >> 2;
    float* sdst = inp_s + srow_ * GD;
    const unsigned int sdst_s = (unsigned int)__cvta_generic_to_shared(sdst);
    const int* idrow = ids + (b0 + srow_)*SEQ;

    // epilogue mapping
    const int eb  = tid >> 3;               // 0..31
    const int ejj = tid & 7;                // 0..7

    float cst  = 0.0f;
    float mmax = -INFINITY;

    // ---- pre-stage embedding for t=0 (plain stores, once) ----
    {
        int id0 = __ldg(idrow + 0);
        const float4* erow = (const float4*)(emb + (size_t)id0 * EMBED);
        #pragma unroll
        for (int o = 0; o < 8; o++) {
            int k4 = (16 + o)*8 + dk;
            *(float4*)(sdst + ((k4 ^ ssw) << 2)) = erow[o*8 + dk];
        }
    }

    // per-replay base snapshot of the half counter (no increments can happen
    // until every CTA passes the ticket barrier below)
    unsigned long long hbase = *((volatile unsigned long long*)hctr);

    ticket_barrier();                        // h(0), emb(0), hbase all settled

    for (int t = 0; t < SEQ; t++) {
        const float* hcur = g_h[t & 1];

        // ---- stage h_prev via cp.async (.cg = L2-direct, no registers) ----
        {
            const float4* hrow = (const float4*)(hcur + (size_t)(b0 + srow_) * HID);
            #pragma unroll
            for (int oct = 0; oct < 16; oct++) {
                int k4 = oct*8 + dk;
                cp16_cg(sdst_s + ((k4 ^ ssw) << 4), hrow + k4);
            }
            CP_COMMIT();
        }
        CP_WAITALL();                        // h(this step) + emb(issued last step)
        __syncthreads();

        // ---- register-tiled split-K GEMM with x prefetch ----
        unsigned long long acc[4][8];
        #pragma unroll
        for (int r = 0; r < 4; r++)
            #pragma unroll
            for (int c = 0; c < 8; c++) acc[r][c] = 0ULL;

        {
            ulonglong2 xa[4], xb[4];
            loadx(xa, xr0, kb, rg);
            #pragma unroll
            for (int kk = 0; kk < 24; kk += 2) {
                loadx(xb, xr0, kb + kk + 1, rg);
                gemm_step(acc, xa, wc0, ((kb+kk)   ^ s0) << 2, ((kb+kk)   ^ s1) << 2);
                if (kk + 2 < 24) loadx(xa, xr0, kb + kk + 2, rg);
                gemm_step(acc, xb, wc0, ((kb+kk+1) ^ s0) << 2, ((kb+kk+1) ^ s1) << 2);
            }
        }

        // ---- one-shot partial store (conflict-free: bank = col'+row) ----
        {
            float* myset = part_s + wid*SET_STRIDE;
            #pragma unroll
            for (int c = 0; c < 8; c++)
                #pragma unroll
                for (int r = 0; r < 4; r++)
                    myset[(4*c + cg)*33 + 4*rg + r] = sum2(acc[r][c]);
        }
        __syncthreads();

        // ---- emb prefetch for t+1: cp.async, no wait until next step top ----
        if (t + 1 < SEQ) {
            int id1 = __ldg(idrow + t + 1);
            const float4* erow = (const float4*)(emb + (size_t)id1 * EMBED);
            #pragma unroll
            for (int o = 0; o < 8; o++) {
                int k4 = (16 + o)*8 + dk;
                cp16_cg(sdst_s + ((k4 ^ ssw) << 4), erow + o*8 + dk);
            }
            CP_COMMIT();
        }

        // ---- epilogue: sum 8 segments, gates, state update ----
        {
            float pf = bias_s[ 0 + ejj];
            float pi = bias_s[ 8 + ejj];
            float po = bias_s[16 + ejj];
            float pg = bias_s[24 + ejj];
            #pragma unroll
            for (int s = 0; s < 8; s++) {
                const float* sp = part_s + s*SET_STRIDE + eb;
                pf += sp[(4*ejj + 0)*33];
                pi += sp[(4*ejj + 1)*33];
                po += sp[(4*ejj + 2)*33];
                pg += sp[(4*ejj + 3)*33];
            }
            float f  = sigf(pf);
            float iv = sigf(pi);
            float o  = sigf(po);
            float gg = tanhfast(pg);
            cst = f*cst + iv*gg;
            float h = o * tanhfast(cst);
            mmax = fmaxf(mmax, h);
            g_h[(t + 1) & 1][(size_t)(b0 + eb)*HID + j0 + ejj] = h;
        }

        // ---- 64-CTA half barrier (skip after the last step) ----
        if (t + 1 < SEQ)
            half_barrier(hctr, hbase + (unsigned long long)HALF_CTAS * (t + 1));
    }

    // ---- max-over-time out, then tiny FC on CTA 0 ----
    g_maxh[(size_t)(b0 + eb)*HID + j0 + ejj] = mmax;
    ticket_barrier();

    if (cta == 0) {
        int b  = tid >> 2;
        int ci = tid & 3;
        const float4* a4 = (const float4*)(g_maxh + (size_t)b * HID);
        const float4* w4 = (const float4*)(fcw + (size_t)ci * HID);
        float acc = fcb[ci];
        #pragma unroll 4
        for (int k = 0; k < HID/4; k++) {
            float4 a = __ldcg(a4 + k);
            float4 w = w4[k];
            acc += a.x*w.x + a.y*w.y + a.z*w.z + a.w*w.w;
        }
        out[b*NCLS + ci] = acc;
    }
}

extern "C" void kernel_launch(void* const* d_in, const int* in_sizes, int n_in,
                              void* d_out, int out_size)
{
    const int*   ids = (const int*)  d_in[0];
    const float* emb = (const float*)d_in[1];
    const float* Wf  = (const float*)d_in[2];
    const float* bf  = (const float*)d_in[3];
    const float* Wi  = (const float*)d_in[4];
    const float* bi  = (const float*)d_in[5];
    const float* Wo  = (const float*)d_in[6];
    const float* bo  = (const float*)d_in[7];
    const float* Wc  = (const float*)d_in[8];
    const float* bc  = (const float*)d_in[9];
    const float* fcw = (const float*)d_in[10];
    const float* fcb = (const float*)d_in[11];
    float* out = (float*)d_out;

    cudaFuncSetAttribute(lstm_persistent,
                         cudaFuncAttributeMaxDynamicSharedMemorySize, SMEM_BYTES);
    lstm_persistent<<<NBLK, NTHR, SMEM_BYTES>>>(ids, emb, Wf, bf, Wi, bi,
                                                Wo, bo, Wc, bc, fcw, fcb, out);
}